// round 11
// baseline (speedup 1.0000x reference)
#include <cuda_runtime.h>
#include <cuda_bf16.h>
#include <math_constants.h>
#include <cstdint>

// ---------------- problem constants ----------------
#define BATCH_B   4
#define NB        4096
#define NPTS      (BATCH_B * NB)       // 16384
#define MBQ       1024
#define MTOT      (BATCH_B * MBQ)      // 4096
#define DIN       64
#define KNB       64
#define H1        128
#define H2        128
#define H3        256
#define LDA       136                  // padded A row stride (bf16 elems)

#define POS_OFF      ((size_t)MTOT * H3)
#define POS_ELEMS    ((size_t)MTOT * 3)
#define BATCH_OFF    (POS_OFF + POS_ELEMS)
#define BATCH_ELEMS  ((size_t)MTOT)

// ---------------- device scratch ----------------
__device__ int   g_sel[MTOT];
__device__ float g_qpos[MTOT * 3];
__device__ int   g_nbr[MTOT * KNB];
__device__ int   g_cnt[MTOT];
__device__ float g_xw1[(size_t)NPTS * H1];
// MMA-fragment-order weight images (uint2 per (ktile*NT + ntile, lane))
__device__ __align__(16) uint2 g_w2f_hi[8 * 16 * 32];
__device__ __align__(16) uint2 g_w2f_lo[8 * 16 * 32];
__device__ __align__(16) uint2 g_w3f_hi[8 * 32 * 32];
__device__ __align__(16) uint2 g_w3f_lo[8 * 32 * 32];

// exact mul-then-add (match XLA square->sum, no FMA contraction)
__device__ __forceinline__ float d2_exact(float dx, float dy, float dz) {
    return __fadd_rn(__fadd_rn(__fmul_rn(dx, dx), __fmul_rn(dy, dy)), __fmul_rn(dz, dz));
}

// ---- packed f32x2 helpers (FPS) ----
__device__ __forceinline__ unsigned long long pack2(float lo, float hi) {
    unsigned long long r;
    asm("mov.b64 %0, {%1, %2};" : "=l"(r) : "f"(lo), "f"(hi));
    return r;
}
__device__ __forceinline__ void unpack2(unsigned long long v, float& lo, float& hi) {
    asm("mov.b64 {%0, %1}, %2;" : "=f"(lo), "=f"(hi) : "l"(v));
}
__device__ __forceinline__ unsigned long long add2(unsigned long long a, unsigned long long b) {
    unsigned long long r;
    asm("add.rn.f32x2 %0, %1, %2;" : "=l"(r) : "l"(a), "l"(b));
    return r;
}
__device__ __forceinline__ unsigned long long mul2(unsigned long long a, unsigned long long b) {
    unsigned long long r;
    asm("mul.rn.f32x2 %0, %1, %2;" : "=l"(r) : "l"(a), "l"(b));
    return r;
}

// ---- mma/ldmatrix helpers (portable PTX) ----
__device__ __forceinline__ uint32_t smem_u32(const void* p) {
    uint32_t a;
    asm("{ .reg .u64 t; cvta.to.shared.u64 t, %1; cvt.u32.u64 %0, t; }" : "=r"(a) : "l"(p));
    return a;
}
__device__ __forceinline__ void ldmat4(uint32_t* r, uint32_t a) {
    asm volatile("ldmatrix.sync.aligned.m8n8.x4.shared.b16 {%0,%1,%2,%3}, [%4];"
                 : "=r"(r[0]), "=r"(r[1]), "=r"(r[2]), "=r"(r[3]) : "r"(a));
}
__device__ __forceinline__ void mma16816(float* d, const uint32_t* a, uint32_t b0, uint32_t b1) {
    asm volatile(
        "mma.sync.aligned.m16n8k16.row.col.f32.bf16.bf16.f32 "
        "{%0,%1,%2,%3}, {%4,%5,%6,%7}, {%8,%9}, {%0,%1,%2,%3};"
        : "+f"(d[0]), "+f"(d[1]), "+f"(d[2]), "+f"(d[3])
        : "r"(a[0]), "r"(a[1]), "r"(a[2]), "r"(a[3]), "r"(b0), "r"(b1));
}
__device__ __forceinline__ void split_bf16(float v, __nv_bfloat16& hi, __nv_bfloat16& lo) {
    hi = __float2bfloat16_rn(v);
    lo = __float2bfloat16_rn(v - __bfloat162float(hi));
}
__device__ __forceinline__ uint32_t packbf(__nv_bfloat16 a, __nv_bfloat16 b) {
    __nv_bfloat162 t;
    t.x = a; t.y = b;
    return *(uint32_t*)&t;
}

// ================= 1) fused: FPS (blocks 0-3, 512 thr) + prep (4..147) ======
#define FPT 8
#define NPREP 144
__global__ __launch_bounds__(512, 1)
void fused_fps_prep(const float* __restrict__ pos, const float* __restrict__ x,
                    const float* __restrict__ W1, const float* __restrict__ b1,
                    const float* __restrict__ W2, const float* __restrict__ W3) {
    __shared__ float spx[NB], spy[NB], spz[NB];
    __shared__ unsigned long long sled[2][16];

    if (blockIdx.x < 4) {
        // ---------------- FPS: 512 threads, 8 pts/thread ----------------
        const int b    = blockIdx.x;
        const int tid  = threadIdx.x;
        const int lane = tid & 31;
        const int warp = tid >> 5;       // 0..15
        const float* p = pos + (size_t)b * NB * 3;

        unsigned long long ppx[FPT / 2], ppy[FPT / 2], ppz[FPT / 2];
        float dd[FPT];
        {
            float tx[FPT], ty[FPT], tz[FPT];
#pragma unroll
            for (int u = 0; u < FPT; u++) {
                const int j = u * 512 + tid;
                tx[u] = p[j * 3 + 0];
                ty[u] = p[j * 3 + 1];
                tz[u] = p[j * 3 + 2];
                spx[j] = tx[u]; spy[j] = ty[u]; spz[j] = tz[u];
                dd[u] = CUDART_INF_F;
            }
#pragma unroll
            for (int q = 0; q < FPT / 2; q++) {
                ppx[q] = pack2(tx[2 * q], tx[2 * q + 1]);
                ppy[q] = pack2(ty[2 * q], ty[2 * q + 1]);
                ppz[q] = pack2(tz[2 * q], tz[2 * q + 1]);
            }
        }
        if (tid == 0) g_sel[b * MBQ] = 0;
        __syncthreads();

        float cx = spx[0], cy = spy[0], cz = spz[0];

        for (int k = 1; k < MBQ; k++) {
            const unsigned long long ncx = pack2(-cx, -cx);
            const unsigned long long ncy = pack2(-cy, -cy);
            const unsigned long long ncz = pack2(-cz, -cz);
#pragma unroll
            for (int q = 0; q < FPT / 2; q++) {
                unsigned long long dx = add2(ppx[q], ncx);
                unsigned long long dy = add2(ppy[q], ncy);
                unsigned long long dz = add2(ppz[q], ncz);
                unsigned long long s  = add2(add2(mul2(dx, dx), mul2(dy, dy)), mul2(dz, dz));
                float d0, d1;
                unpack2(s, d0, d1);
                dd[2 * q]     = fminf(dd[2 * q], d0);
                dd[2 * q + 1] = fminf(dd[2 * q + 1], d1);
            }
            // local argmax tree over 8, keep-left on tie (= smallest index)
            float tv[FPT]; int tu[FPT];
#pragma unroll
            for (int u = 0; u < FPT; u++) { tv[u] = dd[u]; tu[u] = u; }
#pragma unroll
            for (int step = 1; step < FPT; step <<= 1) {
#pragma unroll
                for (int u = 0; u < FPT; u += 2 * step) {
                    const bool take = tv[u + step] > tv[u];
                    tv[u] = take ? tv[u + step] : tv[u];
                    tu[u] = take ? tu[u + step] : tu[u];
                }
            }
            const int myidx = tu[0] * 512 + tid;
            const unsigned vb = __float_as_uint(tv[0]);   // d2>=0: uint order == float order
            const unsigned mx = __reduce_max_sync(0xffffffffu, vb);
            const unsigned cand = (vb == mx) ? (unsigned)myidx : 0xffffffffu;
            const unsigned imin = __reduce_min_sync(0xffffffffu, cand);

            const int par = k & 1;
            if (lane == 0)
                sled[par][warp] = ((unsigned long long)mx << 32) | (unsigned)(NB - 1 - imin);
            __syncthreads();

            unsigned long long m = sled[par][0];
#pragma unroll
            for (int w = 1; w < 16; w++) {
                unsigned long long o = sled[par][w];
                if (o > m) m = o;
            }
            const int widx = NB - 1 - (int)(unsigned)(m & 0xffffffffu);
            if (tid == 0) g_sel[b * MBQ + k] = widx;
            cx = spx[widx]; cy = spy[widx]; cz = spz[widx];
        }
    } else {
        // ---------------- prep: xw1 + weight fragment images ----------------
        const int pb  = blockIdx.x - 4;
        const int tid = threadIdx.x;
        const int t   = tid & 127;
        const int rh  = tid >> 7;      // 0..3

        for (int rp = pb; rp < NPTS / 4; rp += NPREP) {
            const int row = rp * 4 + rh;
            float acc = __ldg(&b1[t]);
            const float* xr = x + (size_t)row * DIN;
#pragma unroll 8
            for (int i = 0; i < DIN; i++)
                acc = fmaf(__ldg(&xr[i]), __ldg(&W1[i * H1 + t]), acc);
            g_xw1[(size_t)row * H1 + t] = acc;
        }

        for (int idx = pb * 512 + tid; idx < 8192 + 16384; idx += NPREP * 512) {
            if (idx < 8192) {
                const int r  = idx & 1;
                const int l  = (idx >> 1) & 31;
                const int nt = (idx >> 6) & 15;
                const int kt = idx >> 10;
                const int k  = kt * 16 + (l & 3) * 2 + r * 8;
                const int n  = nt * 8 + (l >> 2);
                __nv_bfloat16 h0, l0, h1, l1;
                split_bf16(__ldg(&W2[k * H2 + n]), h0, l0);
                split_bf16(__ldg(&W2[(k + 1) * H2 + n]), h1, l1);
                ((uint32_t*)g_w2f_hi)[idx] = packbf(h0, h1);
                ((uint32_t*)g_w2f_lo)[idx] = packbf(l0, l1);
            } else {
                const int i2 = idx - 8192;
                const int r  = i2 & 1;
                const int l  = (i2 >> 1) & 31;
                const int nt = (i2 >> 6) & 31;
                const int kt = i2 >> 11;
                const int k  = kt * 16 + (l & 3) * 2 + r * 8;
                const int n  = nt * 8 + (l >> 2);
                __nv_bfloat16 h0, l0, h1, l1;
                split_bf16(__ldg(&W3[k * H3 + n]), h0, l0);
                split_bf16(__ldg(&W3[(k + 1) * H3 + n]), h1, l1);
                ((uint32_t*)g_w3f_hi)[i2] = packbf(h0, h1);
                ((uint32_t*)g_w3f_lo)[i2] = packbf(l0, l1);
            }
        }
    }
}

// ================= 2) Radius search (first K in index order) =================
__global__ __launch_bounds__(256)
void radius_kernel(const float* __restrict__ pos, float* __restrict__ out, long long out_size) {
    const int warp = (blockIdx.x * blockDim.x + threadIdx.x) >> 5;
    const int lane = threadIdx.x & 31;
    if (warp >= MTOT) return;
    const int b  = warp >> 10;
    const float* p = pos + (size_t)b * NB * 3;

    const int selIdx = g_sel[warp];
    const float qx = p[selIdx * 3 + 0];
    const float qy = p[selIdx * 3 + 1];
    const float qz = p[selIdx * 3 + 2];

    if (lane == 0) {
        g_qpos[warp * 3 + 0] = qx;
        g_qpos[warp * 3 + 1] = qy;
        g_qpos[warp * 3 + 2] = qz;
        if (out_size >= (long long)(POS_OFF + POS_ELEMS)) {
            out[POS_OFF + (size_t)warp * 3 + 0] = qx;
            out[POS_OFF + (size_t)warp * 3 + 1] = qy;
            out[POS_OFF + (size_t)warp * 3 + 2] = qz;
        }
        if (out_size >= (long long)(BATCH_OFF + BATCH_ELEMS)) {
            out[BATCH_OFF + warp] = (float)b;
        }
    }

    const float R2 = 0.04f;
    int cnt = 0;
    for (int base = 0; base < NB; base += 32) {
        const int j = base + lane;
        float d2 = d2_exact(p[j * 3 + 0] - qx, p[j * 3 + 1] - qy, p[j * 3 + 2] - qz);
        const bool in = (d2 <= R2);
        const unsigned msk = __ballot_sync(0xffffffffu, in);
        if (in) {
            int r = cnt + __popc(msk & ((1u << lane) - 1u));
            if (r < KNB) g_nbr[warp * KNB + r] = j;
        }
        cnt += __popc(msk);
        if (cnt >= KNB) break;
    }
    if (lane == 0) g_cnt[warp] = cnt < KNB ? cnt : KNB;
}

// ================= 3) Conv: smem = A only; B from gmem fragments =============
// Block = 2 centroids (M=128), 256 threads = 8 warps, 2 blocks/SM.
#define OFF_A_HI   0
#define OFF_A_LO   34816
#define OFF_W1R    69632
#define CONV_SMEM  (69632 + 1536)

__global__ __launch_bounds__(256, 2)
void conv_kernel(const float* __restrict__ pos, const float* __restrict__ W1,
                 const float* __restrict__ b2, const float* __restrict__ b3,
                 float* __restrict__ out) {
    extern __shared__ char sm[];
    const uint32_t sb = smem_u32(sm);
    __nv_bfloat16* Ahi = (__nv_bfloat16*)(sm + OFF_A_HI);
    __nv_bfloat16* Alo = (__nv_bfloat16*)(sm + OFF_A_LO);
    float* w1r = (float*)(sm + OFF_W1R);

    const int tid  = threadIdx.x;
    const int warp = tid >> 5;
    const int lane = tid & 31;
    const int g    = lane >> 2;
    const int tg   = lane & 3;
    const int wm   = warp & 1;
    const int wn   = warp >> 1;
    const int c0   = blockIdx.x * 2;
    const int gp   = (c0 >> 10) * NB;

    if (tid < 128) {
        w1r[tid]       = __ldg(&W1[64 * H1 + tid]);
        w1r[128 + tid] = __ldg(&W1[65 * H1 + tid]);
        w1r[256 + tid] = __ldg(&W1[66 * H1 + tid]);
    }
    __syncthreads();

    // ---- phase 1: build A = h1 split (hi/lo bf16) ----
    {
        const int m    = tid >> 1;
        const int hf   = tid & 1;
        const int half = m >> 6;
        const int slot = m & 63;
        const int ci   = c0 + half;
        const int cnt  = g_cnt[ci];
        const bool valid = slot < cnt;
        const int j = valid ? (g_nbr[ci * KNB + slot] + gp) : gp;
        const float rx = __ldg(&pos[j * 3 + 0]) - g_qpos[ci * 3 + 0];
        const float ry = __ldg(&pos[j * 3 + 1]) - g_qpos[ci * 3 + 1];
        const float rz = __ldg(&pos[j * 3 + 2]) - g_qpos[ci * 3 + 2];
        const float* xrow = g_xw1 + (size_t)j * H1;
#pragma unroll 4
        for (int c4 = hf * 64; c4 < hf * 64 + 64; c4 += 4) {
            const float4 xv = __ldg((const float4*)(xrow + c4));
            const float xe[4] = {xv.x, xv.y, xv.z, xv.w};
            __nv_bfloat16 hi[4], lo[4];
#pragma unroll
            for (int e = 0; e < 4; e++) {
                const int t = c4 + e;
                float v = xe[e];
                v = fmaf(rx, w1r[t], v);
                v = fmaf(ry, w1r[128 + t], v);
                v = fmaf(rz, w1r[256 + t], v);
                v = fmaxf(v, 0.0f);
                if (!valid) v = 0.0f;
                split_bf16(v, hi[e], lo[e]);
            }
            *(uint32_t*)(Ahi + m * LDA + c4)     = packbf(hi[0], hi[1]);
            *(uint32_t*)(Ahi + m * LDA + c4 + 2) = packbf(hi[2], hi[3]);
            *(uint32_t*)(Alo + m * LDA + c4)     = packbf(lo[0], lo[1]);
            *(uint32_t*)(Alo + m * LDA + c4 + 2) = packbf(lo[2], lo[3]);
        }
    }
    __syncthreads();

    const uint32_t aAhi = sb + OFF_A_HI, aAlo = sb + OFF_A_LO;

    // ---- GEMM1: 128x128x128, warp tile 64m x 32n, B prefetch ping-pong ----
    float d1r[4][4][4] = {};
    {
        uint2 bh[4], bl[4];
#pragma unroll
        for (int nf = 0; nf < 4; nf++) {
            const int idx = (wn * 4 + nf) * 32 + lane;
            bh[nf] = __ldg(&g_w2f_hi[idx]);
            bl[nf] = __ldg(&g_w2f_lo[idx]);
        }
#pragma unroll
        for (int ks = 0; ks < 8; ks++) {
            uint2 nbh[4], nbl[4];
            if (ks < 7) {
#pragma unroll
                for (int nf = 0; nf < 4; nf++) {
                    const int idx = ((ks + 1) * 16 + wn * 4 + nf) * 32 + lane;
                    nbh[nf] = __ldg(&g_w2f_hi[idx]);
                    nbl[nf] = __ldg(&g_w2f_lo[idx]);
                }
            }
            const uint32_t colo = (uint32_t)(ks * 16 + (lane >> 4) * 8) * 2;
#pragma unroll
            for (int mf = 0; mf < 4; mf++) {
                const uint32_t ro = (uint32_t)(wm * 64 + mf * 16 + (lane & 15)) * (LDA * 2);
                uint32_t ah[4], al[4];
                ldmat4(ah, aAhi + ro + colo);
                ldmat4(al, aAlo + ro + colo);
#pragma unroll
                for (int nf = 0; nf < 4; nf++) {
                    mma16816(d1r[mf][nf], ah, bh[nf].x, bh[nf].y);
                    mma16816(d1r[mf][nf], ah, bl[nf].x, bl[nf].y);
                    mma16816(d1r[mf][nf], al, bh[nf].x, bh[nf].y);
                }
            }
            if (ks < 7) {
#pragma unroll
                for (int nf = 0; nf < 4; nf++) { bh[nf] = nbh[nf]; bl[nf] = nbl[nf]; }
            }
        }
    }
    __syncthreads();   // all reads of A(h1) done before overwrite

    // ---- epilogue 1: h2 = relu(D1 + b2) -> split back into A in place ----
    {
#pragma unroll
        for (int mf = 0; mf < 4; mf++) {
            const int row0 = wm * 64 + mf * 16 + g;
#pragma unroll
            for (int nf = 0; nf < 4; nf++) {
                const int col = wn * 32 + nf * 8 + tg * 2;
                const float bb0 = __ldg(&b2[col]);
                const float bb1 = __ldg(&b2[col + 1]);
                const float v00 = fmaxf(d1r[mf][nf][0] + bb0, 0.0f);
                const float v01 = fmaxf(d1r[mf][nf][1] + bb1, 0.0f);
                const float v10 = fmaxf(d1r[mf][nf][2] + bb0, 0.0f);
                const float v11 = fmaxf(d1r[mf][nf][3] + bb1, 0.0f);
                __nv_bfloat16 h0, l0, h1b, l1b, h2b, l2b, h3b, l3b;
                split_bf16(v00, h0, l0);
                split_bf16(v01, h1b, l1b);
                split_bf16(v10, h2b, l2b);
                split_bf16(v11, h3b, l3b);
                *(uint32_t*)(Ahi + row0 * LDA + col)       = packbf(h0, h1b);
                *(uint32_t*)(Alo + row0 * LDA + col)       = packbf(l0, l1b);
                *(uint32_t*)(Ahi + (row0 + 8) * LDA + col) = packbf(h2b, h3b);
                *(uint32_t*)(Alo + (row0 + 8) * LDA + col) = packbf(l2b, l3b);
            }
        }
    }
    __syncthreads();

    // ---- GEMM2 (128x256x128) + fused masked max; B prefetch ping-pong ----
    const int count = g_cnt[c0 + wm];
#pragma unroll
    for (int rep = 0; rep < 2; rep++) {
        float d2r[4][4][4] = {};
        uint2 bh[4], bl[4];
#pragma unroll
        for (int nf = 0; nf < 4; nf++) {
            const int idx = (rep * 16 + wn * 4 + nf) * 32 + lane;
            bh[nf] = __ldg(&g_w3f_hi[idx]);
            bl[nf] = __ldg(&g_w3f_lo[idx]);
        }
#pragma unroll
        for (int ks = 0; ks < 8; ks++) {
            uint2 nbh[4], nbl[4];
            if (ks < 7) {
#pragma unroll
                for (int nf = 0; nf < 4; nf++) {
                    const int idx = ((ks + 1) * 32 + rep * 16 + wn * 4 + nf) * 32 + lane;
                    nbh[nf] = __ldg(&g_w3f_hi[idx]);
                    nbl[nf] = __ldg(&g_w3f_lo[idx]);
                }
            }
            const uint32_t colo = (uint32_t)(ks * 16 + (lane >> 4) * 8) * 2;
#pragma unroll
            for (int mf = 0; mf < 4; mf++) {
                const uint32_t ro = (uint32_t)(wm * 64 + mf * 16 + (lane & 15)) * (LDA * 2);
                uint32_t ah[4], al[4];
                ldmat4(ah, aAhi + ro + colo);
                ldmat4(al, aAlo + ro + colo);
#pragma unroll
                for (int nf = 0; nf < 4; nf++) {
                    mma16816(d2r[mf][nf], ah, bh[nf].x, bh[nf].y);
                    mma16816(d2r[mf][nf], ah, bl[nf].x, bl[nf].y);
                    mma16816(d2r[mf][nf], al, bh[nf].x, bh[nf].y);
                }
            }
            if (ks < 7) {
#pragma unroll
                for (int nf = 0; nf < 4; nf++) { bh[nf] = nbh[nf]; bl[nf] = nbl[nf]; }
            }
        }
#pragma unroll
        for (int nf = 0; nf < 4; nf++) {
            float mx0 = -CUDART_INF_F, mx1 = -CUDART_INF_F;
#pragma unroll
            for (int mf = 0; mf < 4; mf++) {
                const int r1 = mf * 16 + g;
                if (r1 < count)     { mx0 = fmaxf(mx0, d2r[mf][nf][0]); mx1 = fmaxf(mx1, d2r[mf][nf][1]); }
                if (r1 + 8 < count) { mx0 = fmaxf(mx0, d2r[mf][nf][2]); mx1 = fmaxf(mx1, d2r[mf][nf][3]); }
            }
#pragma unroll
            for (int off = 4; off <= 16; off <<= 1) {
                mx0 = fmaxf(mx0, __shfl_xor_sync(0xffffffffu, mx0, off));
                mx1 = fmaxf(mx1, __shfl_xor_sync(0xffffffffu, mx1, off));
            }
            if (g == 0) {
                const int col = rep * 128 + wn * 32 + nf * 8 + tg * 2;
                out[(size_t)(c0 + wm) * H3 + col]     = fmaxf(mx0 + __ldg(&b3[col]), 0.0f);
                out[(size_t)(c0 + wm) * H3 + col + 1] = fmaxf(mx1 + __ldg(&b3[col + 1]), 0.0f);
            }
        }
    }
}

// ================= launch =================
extern "C" void kernel_launch(void* const* d_in, const int* in_sizes, int n_in,
                              void* d_out, int out_size) {
    const float* x   = (const float*)d_in[0];
    const float* pos = (const float*)d_in[1];
    // d_in[2] = batch (int32), unused: clouds contiguous & equal-sized
    const float* W1  = (const float*)d_in[3];
    const float* b1  = (const float*)d_in[4];
    const float* W2  = (const float*)d_in[5];
    const float* b2  = (const float*)d_in[6];
    const float* W3  = (const float*)d_in[7];
    const float* b3  = (const float*)d_in[8];
    float* out = (float*)d_out;

    cudaFuncSetAttribute(conv_kernel, cudaFuncAttributeMaxDynamicSharedMemorySize, CONV_SMEM);

    fused_fps_prep<<<4 + NPREP, 512>>>(pos, x, W1, b1, W2, W3);
    radius_kernel<<<MTOT / 8, 256>>>(pos, out, (long long)out_size);
    conv_kernel<<<MTOT / 2, 256, CONV_SMEM>>>(pos, W1, b2, b3, out);
}

// round 12
// speedup vs baseline: 1.3553x; 1.3553x over previous
#include <cuda_runtime.h>
#include <cuda_bf16.h>
#include <math_constants.h>
#include <cstdint>

// ---------------- problem constants ----------------
#define BATCH_B   4
#define NB        4096
#define NPTS      (BATCH_B * NB)       // 16384
#define MBQ       1024
#define MTOT      (BATCH_B * MBQ)      // 4096
#define DIN       64
#define KNB       64
#define H1        128
#define H2        128
#define H3        256
#define LDA       136                  // padded A row stride (bf16 elems)

#define POS_OFF      ((size_t)MTOT * H3)
#define POS_ELEMS    ((size_t)MTOT * 3)
#define BATCH_OFF    (POS_OFF + POS_ELEMS)
#define BATCH_ELEMS  ((size_t)MTOT)

// ---------------- device scratch ----------------
__device__ int   g_sel[MTOT];
__device__ float g_xw1[(size_t)NPTS * H1];
// MMA-fragment-order weight images (uint2 per (ktile*NT + ntile, lane))
__device__ __align__(16) uint2 g_w2f_hi[8 * 16 * 32];
__device__ __align__(16) uint2 g_w2f_lo[8 * 16 * 32];
__device__ __align__(16) uint2 g_w3f_hi[8 * 32 * 32];
__device__ __align__(16) uint2 g_w3f_lo[8 * 32 * 32];

// exact mul-then-add (match XLA square->sum, no FMA contraction)
__device__ __forceinline__ float d2_exact(float dx, float dy, float dz) {
    return __fadd_rn(__fadd_rn(__fmul_rn(dx, dx), __fmul_rn(dy, dy)), __fmul_rn(dz, dz));
}

// ---- packed f32x2 helpers (FPS) ----
__device__ __forceinline__ unsigned long long pack2(float lo, float hi) {
    unsigned long long r;
    asm("mov.b64 %0, {%1, %2};" : "=l"(r) : "f"(lo), "f"(hi));
    return r;
}
__device__ __forceinline__ void unpack2(unsigned long long v, float& lo, float& hi) {
    asm("mov.b64 {%0, %1}, %2;" : "=f"(lo), "=f"(hi) : "l"(v));
}
__device__ __forceinline__ unsigned long long add2(unsigned long long a, unsigned long long b) {
    unsigned long long r;
    asm("add.rn.f32x2 %0, %1, %2;" : "=l"(r) : "l"(a), "l"(b));
    return r;
}
__device__ __forceinline__ unsigned long long mul2(unsigned long long a, unsigned long long b) {
    unsigned long long r;
    asm("mul.rn.f32x2 %0, %1, %2;" : "=l"(r) : "l"(a), "l"(b));
    return r;
}

// ---- mma/ldmatrix helpers (portable PTX) ----
__device__ __forceinline__ uint32_t smem_u32(const void* p) {
    uint32_t a;
    asm("{ .reg .u64 t; cvta.to.shared.u64 t, %1; cvt.u32.u64 %0, t; }" : "=r"(a) : "l"(p));
    return a;
}
__device__ __forceinline__ void ldmat4(uint32_t* r, uint32_t a) {
    asm volatile("ldmatrix.sync.aligned.m8n8.x4.shared.b16 {%0,%1,%2,%3}, [%4];"
                 : "=r"(r[0]), "=r"(r[1]), "=r"(r[2]), "=r"(r[3]) : "r"(a));
}
__device__ __forceinline__ void mma16816(float* d, const uint32_t* a, uint32_t b0, uint32_t b1) {
    asm volatile(
        "mma.sync.aligned.m16n8k16.row.col.f32.bf16.bf16.f32 "
        "{%0,%1,%2,%3}, {%4,%5,%6,%7}, {%8,%9}, {%0,%1,%2,%3};"
        : "+f"(d[0]), "+f"(d[1]), "+f"(d[2]), "+f"(d[3])
        : "r"(a[0]), "r"(a[1]), "r"(a[2]), "r"(a[3]), "r"(b0), "r"(b1));
}
__device__ __forceinline__ void split_bf16(float v, __nv_bfloat16& hi, __nv_bfloat16& lo) {
    hi = __float2bfloat16_rn(v);
    lo = __float2bfloat16_rn(v - __bfloat162float(hi));
}
__device__ __forceinline__ uint32_t packbf(__nv_bfloat16 a, __nv_bfloat16 b) {
    __nv_bfloat162 t;
    t.x = a; t.y = b;
    return *(uint32_t*)&t;
}

// ================= 1) fused: FPS (blocks 0-3) + xw1/W-frag prep (4..147) ====
#define FPT 16
#define NPREP 144
__global__ __launch_bounds__(256, 1)
void fused_fps_prep(const float* __restrict__ pos, const float* __restrict__ x,
                    const float* __restrict__ W1, const float* __restrict__ b1,
                    const float* __restrict__ W2, const float* __restrict__ W3) {
    __shared__ float spx[NB], spy[NB], spz[NB];
    __shared__ unsigned long long sled[2][8];

    if (blockIdx.x < 4) {
        // ---------------- FPS ----------------
        const int b    = blockIdx.x;
        const int tid  = threadIdx.x;
        const int lane = tid & 31;
        const int warp = tid >> 5;
        const float* p = pos + (size_t)b * NB * 3;

        unsigned long long ppx[FPT / 2], ppy[FPT / 2], ppz[FPT / 2];
        float dd[FPT];
        {
            float tx[FPT], ty[FPT], tz[FPT];
#pragma unroll
            for (int u = 0; u < FPT; u++) {
                const int j = u * 256 + tid;
                tx[u] = p[j * 3 + 0];
                ty[u] = p[j * 3 + 1];
                tz[u] = p[j * 3 + 2];
                spx[j] = tx[u]; spy[j] = ty[u]; spz[j] = tz[u];
                dd[u] = CUDART_INF_F;
            }
#pragma unroll
            for (int q = 0; q < FPT / 2; q++) {
                ppx[q] = pack2(tx[2 * q], tx[2 * q + 1]);
                ppy[q] = pack2(ty[2 * q], ty[2 * q + 1]);
                ppz[q] = pack2(tz[2 * q], tz[2 * q + 1]);
            }
        }
        if (tid == 0) g_sel[b * MBQ] = 0;
        __syncthreads();

        float cx = spx[0], cy = spy[0], cz = spz[0];

        for (int k = 1; k < MBQ; k++) {
            const unsigned long long ncx = pack2(-cx, -cx);
            const unsigned long long ncy = pack2(-cy, -cy);
            const unsigned long long ncz = pack2(-cz, -cz);
#pragma unroll
            for (int q = 0; q < FPT / 2; q++) {
                unsigned long long dx = add2(ppx[q], ncx);
                unsigned long long dy = add2(ppy[q], ncy);
                unsigned long long dz = add2(ppz[q], ncz);
                unsigned long long s  = add2(add2(mul2(dx, dx), mul2(dy, dy)), mul2(dz, dz));
                float d0, d1;
                unpack2(s, d0, d1);
                dd[2 * q]     = fminf(dd[2 * q], d0);
                dd[2 * q + 1] = fminf(dd[2 * q + 1], d1);
            }
            float tv[FPT]; int tu[FPT];
#pragma unroll
            for (int u = 0; u < FPT; u++) { tv[u] = dd[u]; tu[u] = u; }
#pragma unroll
            for (int step = 1; step < FPT; step <<= 1) {
#pragma unroll
                for (int u = 0; u < FPT; u += 2 * step) {
                    const bool take = tv[u + step] > tv[u];
                    tv[u] = take ? tv[u + step] : tv[u];
                    tu[u] = take ? tu[u + step] : tu[u];
                }
            }
            const int myidx = tu[0] * 256 + tid;
            const unsigned vb = __float_as_uint(tv[0]);   // d2>=0: uint order == float order
            const unsigned mx = __reduce_max_sync(0xffffffffu, vb);
            const unsigned cand = (vb == mx) ? (unsigned)myidx : 0xffffffffu;
            const unsigned imin = __reduce_min_sync(0xffffffffu, cand);

            const int par = k & 1;
            if (lane == 0)
                sled[par][warp] = ((unsigned long long)mx << 32) | (unsigned)(NB - 1 - imin);
            __syncthreads();

            unsigned long long m = sled[par][0];
#pragma unroll
            for (int w = 1; w < 8; w++) {
                unsigned long long o = sled[par][w];
                if (o > m) m = o;
            }
            const int widx = NB - 1 - (int)(unsigned)(m & 0xffffffffu);
            if (tid == 0) g_sel[b * MBQ + k] = widx;
            cx = spx[widx]; cy = spy[widx]; cz = spz[widx];
        }
    } else {
        // ---------------- prep: xw1 + weight fragment images ----------------
        const int pb  = blockIdx.x - 4;
        const int tid = threadIdx.x;
        const int t   = tid & 127;
        const int rh  = tid >> 7;

        for (int rp = pb; rp < NPTS / 2; rp += NPREP) {
            const int row = rp * 2 + rh;
            float acc = __ldg(&b1[t]);
            const float* xr = x + (size_t)row * DIN;
#pragma unroll 8
            for (int i = 0; i < DIN; i++)
                acc = fmaf(__ldg(&xr[i]), __ldg(&W1[i * H1 + t]), acc);
            g_xw1[(size_t)row * H1 + t] = acc;
        }

        for (int idx = pb * 256 + tid; idx < 8192 + 16384; idx += NPREP * 256) {
            if (idx < 8192) {
                const int r  = idx & 1;
                const int l  = (idx >> 1) & 31;
                const int nt = (idx >> 6) & 15;
                const int kt = idx >> 10;
                const int k  = kt * 16 + (l & 3) * 2 + r * 8;
                const int n  = nt * 8 + (l >> 2);
                __nv_bfloat16 h0, l0, h1, l1;
                split_bf16(__ldg(&W2[k * H2 + n]), h0, l0);
                split_bf16(__ldg(&W2[(k + 1) * H2 + n]), h1, l1);
                ((uint32_t*)g_w2f_hi)[idx] = packbf(h0, h1);
                ((uint32_t*)g_w2f_lo)[idx] = packbf(l0, l1);
            } else {
                const int i2 = idx - 8192;
                const int r  = i2 & 1;
                const int l  = (i2 >> 1) & 31;
                const int nt = (i2 >> 6) & 31;
                const int kt = i2 >> 11;
                const int k  = kt * 16 + (l & 3) * 2 + r * 8;
                const int n  = nt * 8 + (l >> 2);
                __nv_bfloat16 h0, l0, h1, l1;
                split_bf16(__ldg(&W3[k * H3 + n]), h0, l0);
                split_bf16(__ldg(&W3[(k + 1) * H3 + n]), h1, l1);
                ((uint32_t*)g_w3f_hi)[i2] = packbf(h0, h1);
                ((uint32_t*)g_w3f_lo)[i2] = packbf(l0, l1);
            }
        }
    }
}

// ================= 2) Conv with fused radius: smem = A + radius scratch =====
// Block = 2 centroids (M=128), 256 threads = 8 warps, 2 blocks/SM.
#define OFF_A_HI   0        // 34816
#define OFF_A_LO   34816    // 34816
#define OFF_W1R    69632    // 1536
#define OFF_SLAB   71168    // 2048 : int slab[2][4][64]
#define OFF_SLCNT  73216    // 32
#define OFF_NBR    73248    // 512
#define OFF_SCNT   73760    // 8
#define OFF_SQP    73768    // 24
#define CONV_SMEM  73856

__global__ __launch_bounds__(256, 2)
void conv_kernel(const float* __restrict__ pos, const float* __restrict__ W1,
                 const float* __restrict__ b2, const float* __restrict__ b3,
                 float* __restrict__ out, long long out_size) {
    extern __shared__ char sm[];
    const uint32_t sb = smem_u32(sm);
    __nv_bfloat16* Ahi = (__nv_bfloat16*)(sm + OFF_A_HI);
    __nv_bfloat16* Alo = (__nv_bfloat16*)(sm + OFF_A_LO);
    float* w1r   = (float*)(sm + OFF_W1R);
    int*   slab  = (int*)(sm + OFF_SLAB);
    int*   slcnt = (int*)(sm + OFF_SLCNT);
    int*   snbr  = (int*)(sm + OFF_NBR);
    int*   scnt  = (int*)(sm + OFF_SCNT);
    float* sqp   = (float*)(sm + OFF_SQP);

    const int tid  = threadIdx.x;
    const int warp = tid >> 5;
    const int lane = tid & 31;
    const int g    = lane >> 2;
    const int tg   = lane & 3;
    const int wm   = warp & 1;
    const int wn   = warp >> 1;
    const int c0   = blockIdx.x * 2;
    const int cloud = c0 >> 10;
    const int gp   = cloud * NB;
    const float* pp = pos + (size_t)gp * 3;

    if (tid < 128) {
        w1r[tid]       = __ldg(&W1[64 * H1 + tid]);
        w1r[128 + tid] = __ldg(&W1[65 * H1 + tid]);
        w1r[256 + tid] = __ldg(&W1[66 * H1 + tid]);
    }

    // ---- fused radius: warp -> (centroid = warp>>2, slab = warp&3) ----
    {
        const int half = warp >> 2;
        const int sl   = warp & 3;
        const int ci   = c0 + half;
        const int sel  = g_sel[ci];
        const float qx = pp[sel * 3 + 0];
        const float qy = pp[sel * 3 + 1];
        const float qz = pp[sel * 3 + 2];
        if (sl == 0 && lane == 0) {
            sqp[half * 3 + 0] = qx;
            sqp[half * 3 + 1] = qy;
            sqp[half * 3 + 2] = qz;
            if (out_size >= (long long)(POS_OFF + POS_ELEMS)) {
                out[POS_OFF + (size_t)ci * 3 + 0] = qx;
                out[POS_OFF + (size_t)ci * 3 + 1] = qy;
                out[POS_OFF + (size_t)ci * 3 + 2] = qz;
            }
            if (out_size >= (long long)(BATCH_OFF + BATCH_ELEMS)) {
                out[BATCH_OFF + ci] = (float)cloud;
            }
        }
        int* sbuf = slab + (half * 4 + sl) * KNB;
        const int sb0 = sl * 1024;
        int cnt = 0;
        for (int it = 0; it < 32; it++) {
            const int j = sb0 + it * 32 + lane;
            const float d2 = d2_exact(pp[j * 3 + 0] - qx, pp[j * 3 + 1] - qy, pp[j * 3 + 2] - qz);
            const bool in = (d2 <= 0.04f);   // f32(0.2*0.2)
            const unsigned msk = __ballot_sync(0xffffffffu, in);
            if (in) {
                const int r = cnt + __popc(msk & ((1u << lane) - 1u));
                if (r < KNB) sbuf[r] = j;
            }
            cnt += __popc(msk);
            if (cnt >= KNB) break;
        }
        if (lane == 0) slcnt[half * 4 + sl] = cnt < KNB ? cnt : KNB;
    }
    __syncthreads();

    // ---- merge slabs (index order preserved by slab concatenation) ----
    if (tid < 128) {
        const int half = tid >> 6;
        const int r    = tid & 63;
        const int* cc = slcnt + half * 4;
        const int cA = cc[0], cB = cc[1], cC = cc[2], cD = cc[3];
        int tot = cA + cB + cC + cD;
        tot = tot < KNB ? tot : KNB;
        if (r == 0) scnt[half] = tot;
        if (r < tot) {
            int s = 0, off = r;
            if (off >= cA) { off -= cA; s = 1;
                if (off >= cB) { off -= cB; s = 2;
                    if (off >= cC) { off -= cC; s = 3; } } }
            snbr[half * KNB + r] = slab[(half * 4 + s) * KNB + off];
        }
    }
    __syncthreads();

    // ---- phase 1: build A = h1 split (hi/lo bf16) ----
    {
        const int m    = tid >> 1;
        const int hf   = tid & 1;
        const int half = m >> 6;
        const int slot = m & 63;
        const int cnt  = scnt[half];
        const bool valid = slot < cnt;
        const int j = valid ? (snbr[half * KNB + slot] + gp) : gp;
        const float rx = __ldg(&pos[j * 3 + 0]) - sqp[half * 3 + 0];
        const float ry = __ldg(&pos[j * 3 + 1]) - sqp[half * 3 + 1];
        const float rz = __ldg(&pos[j * 3 + 2]) - sqp[half * 3 + 2];
        const float* xrow = g_xw1 + (size_t)j * H1;
#pragma unroll 4
        for (int c4 = hf * 64; c4 < hf * 64 + 64; c4 += 4) {
            const float4 xv = __ldg((const float4*)(xrow + c4));
            const float xe[4] = {xv.x, xv.y, xv.z, xv.w};
            __nv_bfloat16 hi[4], lo[4];
#pragma unroll
            for (int e = 0; e < 4; e++) {
                const int t = c4 + e;
                float v = xe[e];
                v = fmaf(rx, w1r[t], v);
                v = fmaf(ry, w1r[128 + t], v);
                v = fmaf(rz, w1r[256 + t], v);
                v = fmaxf(v, 0.0f);
                if (!valid) v = 0.0f;
                split_bf16(v, hi[e], lo[e]);
            }
            *(uint32_t*)(Ahi + m * LDA + c4)     = packbf(hi[0], hi[1]);
            *(uint32_t*)(Ahi + m * LDA + c4 + 2) = packbf(hi[2], hi[3]);
            *(uint32_t*)(Alo + m * LDA + c4)     = packbf(lo[0], lo[1]);
            *(uint32_t*)(Alo + m * LDA + c4 + 2) = packbf(lo[2], lo[3]);
        }
    }
    __syncthreads();

    const uint32_t aAhi = sb + OFF_A_HI, aAlo = sb + OFF_A_LO;

    // ---- GEMM1: 128x128x128, warp tile 64m x 32n, B prefetch ping-pong ----
    float d1r[4][4][4] = {};
    {
        uint2 bh[4], bl[4];
#pragma unroll
        for (int nf = 0; nf < 4; nf++) {
            const int idx = (wn * 4 + nf) * 32 + lane;
            bh[nf] = __ldg(&g_w2f_hi[idx]);
            bl[nf] = __ldg(&g_w2f_lo[idx]);
        }
#pragma unroll
        for (int ks = 0; ks < 8; ks++) {
            uint2 nbh[4], nbl[4];
            if (ks < 7) {
#pragma unroll
                for (int nf = 0; nf < 4; nf++) {
                    const int idx = ((ks + 1) * 16 + wn * 4 + nf) * 32 + lane;
                    nbh[nf] = __ldg(&g_w2f_hi[idx]);
                    nbl[nf] = __ldg(&g_w2f_lo[idx]);
                }
            }
            const uint32_t colo = (uint32_t)(ks * 16 + (lane >> 4) * 8) * 2;
#pragma unroll
            for (int mf = 0; mf < 4; mf++) {
                const uint32_t ro = (uint32_t)(wm * 64 + mf * 16 + (lane & 15)) * (LDA * 2);
                uint32_t ah[4], al[4];
                ldmat4(ah, aAhi + ro + colo);
                ldmat4(al, aAlo + ro + colo);
#pragma unroll
                for (int nf = 0; nf < 4; nf++) {
                    mma16816(d1r[mf][nf], ah, bh[nf].x, bh[nf].y);
                    mma16816(d1r[mf][nf], ah, bl[nf].x, bl[nf].y);
                    mma16816(d1r[mf][nf], al, bh[nf].x, bh[nf].y);
                }
            }
            if (ks < 7) {
#pragma unroll
                for (int nf = 0; nf < 4; nf++) { bh[nf] = nbh[nf]; bl[nf] = nbl[nf]; }
            }
        }
    }
    __syncthreads();   // all reads of A(h1) done before overwrite

    // ---- epilogue 1: h2 = relu(D1 + b2) -> split back into A in place ----
    {
#pragma unroll
        for (int mf = 0; mf < 4; mf++) {
            const int row0 = wm * 64 + mf * 16 + g;
#pragma unroll
            for (int nf = 0; nf < 4; nf++) {
                const int col = wn * 32 + nf * 8 + tg * 2;
                const float bb0 = __ldg(&b2[col]);
                const float bb1 = __ldg(&b2[col + 1]);
                const float v00 = fmaxf(d1r[mf][nf][0] + bb0, 0.0f);
                const float v01 = fmaxf(d1r[mf][nf][1] + bb1, 0.0f);
                const float v10 = fmaxf(d1r[mf][nf][2] + bb0, 0.0f);
                const float v11 = fmaxf(d1r[mf][nf][3] + bb1, 0.0f);
                __nv_bfloat16 h0, l0, h1b, l1b, h2b, l2b, h3b, l3b;
                split_bf16(v00, h0, l0);
                split_bf16(v01, h1b, l1b);
                split_bf16(v10, h2b, l2b);
                split_bf16(v11, h3b, l3b);
                *(uint32_t*)(Ahi + row0 * LDA + col)       = packbf(h0, h1b);
                *(uint32_t*)(Alo + row0 * LDA + col)       = packbf(l0, l1b);
                *(uint32_t*)(Ahi + (row0 + 8) * LDA + col) = packbf(h2b, h3b);
                *(uint32_t*)(Alo + (row0 + 8) * LDA + col) = packbf(l2b, l3b);
            }
        }
    }
    __syncthreads();

    // ---- GEMM2 (128x256x128) + fused masked max; B prefetch ping-pong ----
    const int count = scnt[wm];
#pragma unroll
    for (int rep = 0; rep < 2; rep++) {
        float d2r[4][4][4] = {};
        uint2 bh[4], bl[4];
#pragma unroll
        for (int nf = 0; nf < 4; nf++) {
            const int idx = (rep * 16 + wn * 4 + nf) * 32 + lane;
            bh[nf] = __ldg(&g_w3f_hi[idx]);
            bl[nf] = __ldg(&g_w3f_lo[idx]);
        }
#pragma unroll
        for (int ks = 0; ks < 8; ks++) {
            uint2 nbh[4], nbl[4];
            if (ks < 7) {
#pragma unroll
                for (int nf = 0; nf < 4; nf++) {
                    const int idx = ((ks + 1) * 32 + rep * 16 + wn * 4 + nf) * 32 + lane;
                    nbh[nf] = __ldg(&g_w3f_hi[idx]);
                    nbl[nf] = __ldg(&g_w3f_lo[idx]);
                }
            }
            const uint32_t colo = (uint32_t)(ks * 16 + (lane >> 4) * 8) * 2;
#pragma unroll
            for (int mf = 0; mf < 4; mf++) {
                const uint32_t ro = (uint32_t)(wm * 64 + mf * 16 + (lane & 15)) * (LDA * 2);
                uint32_t ah[4], al[4];
                ldmat4(ah, aAhi + ro + colo);
                ldmat4(al, aAlo + ro + colo);
#pragma unroll
                for (int nf = 0; nf < 4; nf++) {
                    mma16816(d2r[mf][nf], ah, bh[nf].x, bh[nf].y);
                    mma16816(d2r[mf][nf], ah, bl[nf].x, bl[nf].y);
                    mma16816(d2r[mf][nf], al, bh[nf].x, bh[nf].y);
                }
            }
            if (ks < 7) {
#pragma unroll
                for (int nf = 0; nf < 4; nf++) { bh[nf] = nbh[nf]; bl[nf] = nbl[nf]; }
            }
        }
#pragma unroll
        for (int nf = 0; nf < 4; nf++) {
            float mx0 = -CUDART_INF_F, mx1 = -CUDART_INF_F;
#pragma unroll
            for (int mf = 0; mf < 4; mf++) {
                const int r1 = mf * 16 + g;
                if (r1 < count)     { mx0 = fmaxf(mx0, d2r[mf][nf][0]); mx1 = fmaxf(mx1, d2r[mf][nf][1]); }
                if (r1 + 8 < count) { mx0 = fmaxf(mx0, d2r[mf][nf][2]); mx1 = fmaxf(mx1, d2r[mf][nf][3]); }
            }
#pragma unroll
            for (int off = 4; off <= 16; off <<= 1) {
                mx0 = fmaxf(mx0, __shfl_xor_sync(0xffffffffu, mx0, off));
                mx1 = fmaxf(mx1, __shfl_xor_sync(0xffffffffu, mx1, off));
            }
            if (g == 0) {
                const int col = rep * 128 + wn * 32 + nf * 8 + tg * 2;
                out[(size_t)(c0 + wm) * H3 + col]     = fmaxf(mx0 + __ldg(&b3[col]), 0.0f);
                out[(size_t)(c0 + wm) * H3 + col + 1] = fmaxf(mx1 + __ldg(&b3[col + 1]), 0.0f);
            }
        }
    }
}

// ================= launch =================
extern "C" void kernel_launch(void* const* d_in, const int* in_sizes, int n_in,
                              void* d_out, int out_size) {
    const float* x   = (const float*)d_in[0];
    const float* pos = (const float*)d_in[1];
    // d_in[2] = batch (int32), unused: clouds contiguous & equal-sized
    const float* W1  = (const float*)d_in[3];
    const float* b1  = (const float*)d_in[4];
    const float* W2  = (const float*)d_in[5];
    const float* b2  = (const float*)d_in[6];
    const float* W3  = (const float*)d_in[7];
    const float* b3  = (const float*)d_in[8];
    float* out = (float*)d_out;

    cudaFuncSetAttribute(conv_kernel, cudaFuncAttributeMaxDynamicSharedMemorySize, CONV_SMEM);

    fused_fps_prep<<<4 + NPREP, 256>>>(pos, x, W1, b1, W2, W3);
    conv_kernel<<<MTOT / 2, 256, CONV_SMEM>>>(pos, W1, b2, b3, out, (long long)out_size);
}